// round 1
// baseline (speedup 1.0000x reference)
#include <cuda_runtime.h>
#include <cstdint>

// SpiralConv: out[b,n,o] = relu( sum_{s,f} x[b, idx[n,s], f] * W[o, s*128+f] + bias[o] ) * zp[n]
// B=8, N=12000, F=128, S=16, OUT=128  ->  gather-GEMM: M=96000, K=2048, Nout=128

#define BM 128
#define BN 128
#define BK 32

constexpr int Bq = 8, Nq = 12000, Fq = 128, Sq = 16, OUTq = 128;
constexpr int Kq = Sq * Fq;        // 2048
constexpr int Mtot = Bq * Nq;      // 96000
constexpr int NITER = Kq / BK;     // 64
constexpr int LDA = BK + 4;        // 36 floats/row: (4*r + c) % 32 distinct -> conflict-free frag reads

struct SmemLayout {
    float A[2][BM][LDA];   // gathered x tile, [row][k]
    float Bm[2][BN][LDA];  // W tile, [o][k]
    int   idxs[BM][Sq];    // spiral_adj row table for this block
    int   rowb[BM];        // batch index per row
    float bias[OUTq];
};

__device__ __forceinline__ unsigned cvt_tf32(float f) {
    unsigned u;
    asm volatile("cvt.rna.tf32.f32 %0, %1;" : "=r"(u) : "f"(f));
    return u;
}

__device__ __forceinline__ void cp_async16(void* smem_dst, const void* gsrc) {
    unsigned d = (unsigned)__cvta_generic_to_shared(smem_dst);
    asm volatile("cp.async.cg.shared.global [%0], [%1], 16;" :: "r"(d), "l"(gsrc));
}

extern __shared__ char smem_raw[];

__global__ __launch_bounds__(256) void spiral_conv_kernel(
    const float* __restrict__ x,      // [B, N, F]
    const float* __restrict__ W,      // [OUT, K]
    const float* __restrict__ bias,   // [OUT]
    const int*   __restrict__ adj,    // [N, S]
    const float* __restrict__ zp,     // [N]
    float*       __restrict__ out)    // [B, N, OUT]
{
    SmemLayout& sm = *reinterpret_cast<SmemLayout*>(smem_raw);
    const int tid = threadIdx.x;
    const int m0  = blockIdx.x * BM;

    // ---- stage per-block row metadata ----
    for (int i = tid; i < BM * Sq; i += 256) {
        int row = i >> 4, s = i & 15;
        int n = (m0 + row) % Nq;
        sm.idxs[row][s] = adj[n * Sq + s];
    }
    if (tid < BM)   sm.rowb[tid] = (m0 + tid) / Nq;
    if (tid < OUTq) sm.bias[tid] = bias[tid];
    __syncthreads();

    const int lrow = tid >> 3;        // 0..31
    const int lcol = (tid & 7) * 4;   // 0,4,...,28 (floats)

    auto load_stage = [&](int st, int it) {
        const int k0   = it * BK;
        const int sidx = k0 >> 7;     // which spiral neighbor
        const int f0   = k0 & 127;    // feature offset within that neighbor
        #pragma unroll
        for (int j = 0; j < 4; ++j) {
            int row = lrow + j * 32;
            int iv  = sm.idxs[row][sidx];
            const float* src = x + (((long)(sm.rowb[row] * Nq + iv)) << 7) + f0 + lcol;
            cp_async16(&sm.A[st][row][lcol], src);
        }
        #pragma unroll
        for (int j = 0; j < 4; ++j) {
            int o = lrow + j * 32;
            const float* src = W + (long)o * Kq + k0 + lcol;
            cp_async16(&sm.Bm[st][o][lcol], src);
        }
    };

    // ---- 2-stage pipeline prologue ----
    load_stage(0, 0); asm volatile("cp.async.commit_group;");
    load_stage(1, 1); asm volatile("cp.async.commit_group;");

    const int lane = tid & 31;
    const int warp = tid >> 5;
    const int wm = (warp & 3) * 32;   // warp M offset (4 warps over M)
    const int wn = (warp >> 2) * 64;  // warp N offset (2 warps over N)
    const int tr = lane >> 2;         // 0..7
    const int tc = lane & 3;          // 0..3

    float acc[2][8][4];
    #pragma unroll
    for (int a = 0; a < 2; ++a)
        #pragma unroll
        for (int b2 = 0; b2 < 8; ++b2)
            #pragma unroll
            for (int c = 0; c < 4; ++c) acc[a][b2][c] = 0.f;

    // ---- main loop ----
    for (int it = 0; it < NITER; ++it) {
        asm volatile("cp.async.wait_group 1;");
        __syncthreads();
        const int cur = it & 1;

        #pragma unroll
        for (int k8 = 0; k8 < BK / 8; ++k8) {
            const int kb = k8 * 8;
            unsigned af[2][4];
            unsigned bf[8][2];
            #pragma unroll
            for (int mt = 0; mt < 2; ++mt) {
                int r = wm + mt * 16 + tr;
                af[mt][0] = cvt_tf32(sm.A[cur][r    ][kb + tc]);
                af[mt][1] = cvt_tf32(sm.A[cur][r + 8][kb + tc]);
                af[mt][2] = cvt_tf32(sm.A[cur][r    ][kb + tc + 4]);
                af[mt][3] = cvt_tf32(sm.A[cur][r + 8][kb + tc + 4]);
            }
            #pragma unroll
            for (int nt = 0; nt < 8; ++nt) {
                int o = wn + nt * 8 + tr;
                bf[nt][0] = cvt_tf32(sm.Bm[cur][o][kb + tc]);
                bf[nt][1] = cvt_tf32(sm.Bm[cur][o][kb + tc + 4]);
            }
            #pragma unroll
            for (int mt = 0; mt < 2; ++mt)
                #pragma unroll
                for (int nt = 0; nt < 8; ++nt) {
                    asm volatile(
                        "mma.sync.aligned.m16n8k8.row.col.f32.tf32.tf32.f32 "
                        "{%0,%1,%2,%3}, {%4,%5,%6,%7}, {%8,%9}, {%0,%1,%2,%3};"
                        : "+f"(acc[mt][nt][0]), "+f"(acc[mt][nt][1]),
                          "+f"(acc[mt][nt][2]), "+f"(acc[mt][nt][3])
                        : "r"(af[mt][0]), "r"(af[mt][1]), "r"(af[mt][2]), "r"(af[mt][3]),
                          "r"(bf[nt][0]), "r"(bf[nt][1]));
                }
        }

        __syncthreads();
        if (it + 2 < NITER) load_stage(cur, it + 2);
        asm volatile("cp.async.commit_group;");
    }

    // ---- epilogue: bias + relu + zero_padding, write [m, o] ----
    #pragma unroll
    for (int mt = 0; mt < 2; ++mt) {
        #pragma unroll
        for (int h = 0; h < 2; ++h) {
            int m = m0 + wm + mt * 16 + h * 8 + tr;
            int n = m % Nq;
            float z = zp[n];
            float* orow = out + (long)m * OUTq;
            #pragma unroll
            for (int nt = 0; nt < 8; ++nt) {
                int o = wn + nt * 8 + 2 * tc;
                float v0 = acc[mt][nt][h * 2 + 0] + sm.bias[o];
                float v1 = acc[mt][nt][h * 2 + 1] + sm.bias[o + 1];
                v0 = fmaxf(v0, 0.f) * z;
                v1 = fmaxf(v1, 0.f) * z;
                float2 v = make_float2(v0, v1);
                *reinterpret_cast<float2*>(orow + o) = v;
            }
        }
    }
}

extern "C" void kernel_launch(void* const* d_in, const int* in_sizes, int n_in,
                              void* d_out, int out_size) {
    const float* x    = (const float*)d_in[0];
    const float* W    = (const float*)d_in[1];
    const float* bias = (const float*)d_in[2];
    const int*   adj  = (const int*)d_in[3];
    const float* zp   = (const float*)d_in[4];
    float* out = (float*)d_out;

    const size_t smem = sizeof(SmemLayout);  // ~83 KB
    cudaFuncSetAttribute(spiral_conv_kernel,
                         cudaFuncAttributeMaxDynamicSharedMemorySize, (int)smem);
    spiral_conv_kernel<<<Mtot / BM, 256, smem>>>(x, W, bias, adj, zp, out);
}